// round 1
// baseline (speedup 1.0000x reference)
#include <cuda_runtime.h>

#define S 4096
#define L 16
#define WD 128
#define CD 32
#define NF 5
#define KW 5
#define H 32
#define NTAGS 45
#define IN_DIM (WD + NF)   // 133
#define G4 (4 * H)         // 128

// Scratch (device globals; no allocation allowed)
__device__ float g_pre[2][S * G4];   // input projections, fwd/bwd   (4 MB)
__device__ float g_h[2][S * H];      // hidden states, fwd/bwd       (1 MB)

// ---------------------------------------------------------------------------
// Kernel A: per-word embedding gather + char CNN + input projection (both dirs)
// grid = S blocks, 128 threads
// ---------------------------------------------------------------------------
__global__ __launch_bounds__(128) void prep_kernel(
    const int* __restrict__ word_ids, const int* __restrict__ char_ids,
    const float* __restrict__ word_emb, const float* __restrict__ char_emb,
    const float* __restrict__ conv_w, const float* __restrict__ conv_b,
    const float* __restrict__ w_ih_f, const float* __restrict__ b_ih_f,
    const float* __restrict__ b_hh_f,
    const float* __restrict__ w_ih_b, const float* __restrict__ b_ih_b,
    const float* __restrict__ b_hh_b)
{
    __shared__ float rep[IN_DIM];
    __shared__ float ce[L][CD];
    __shared__ float conv_sh[NF][L];

    const int s = blockIdx.x;
    const int j = threadIdx.x;   // 0..127

    // word embedding -> rep[0:128]
    const int wid = word_ids[s];
    rep[j] = word_emb[wid * WD + j];

    // char embeddings: L*CD = 512 floats, 4 per thread
    #pragma unroll
    for (int i = j; i < L * CD; i += 128) {
        const int l = i / CD, c = i % CD;
        const int cid = char_ids[s * L + l];
        ce[l][c] = char_emb[cid * CD + c];
    }
    __syncthreads();

    // conv: NF*L = 80 outputs, one per thread
    if (j < NF * L) {
        const int f = j / L, l = j % L;
        float acc = conv_b[f];
        #pragma unroll
        for (int k = 0; k < KW; k++) {
            const int ll = l + k - 2;
            if (ll >= 0 && ll < L) {
                #pragma unroll
                for (int c = 0; c < CD; c++)
                    acc += ce[ll][c] * conv_w[(f * CD + c) * KW + k];
            }
        }
        conv_sh[f][l] = acc;
    }
    __syncthreads();

    // maxpool over L -> rep[128:133]
    if (j < NF) {
        float m = conv_sh[j][0];
        #pragma unroll
        for (int l = 1; l < L; l++) m = fmaxf(m, conv_sh[j][l]);
        rep[WD + j] = m;
    }
    __syncthreads();

    // input projections: thread j computes pre-gate row j, both directions
    float accf = b_ih_f[j] + b_hh_f[j];
    float accb = b_ih_b[j] + b_hh_b[j];
    const float* wf = w_ih_f + j * IN_DIM;
    const float* wb = w_ih_b + j * IN_DIM;
    #pragma unroll 7
    for (int k = 0; k < IN_DIM; k++) {
        const float r = rep[k];
        accf = fmaf(r, wf[k], accf);
        accb = fmaf(r, wb[k], accb);
    }
    g_pre[0][s * G4 + j] = accf;
    g_pre[1][s * G4 + j] = accb;
}

// ---------------------------------------------------------------------------
// Kernel B: sequential LSTM scan. grid = 2 blocks (dir), 128 threads.
// Thread j owns gate j (row of w_hh in registers). All 4 warps redundantly
// carry (h, c) for unit `lane`; matvec uses intra-warp shuffles of h.
// One __syncthreads per step via ping-pong gate buffer.
// ---------------------------------------------------------------------------
__device__ __forceinline__ float fast_sigmoid(float x) {
    return 1.0f / (1.0f + __expf(-x));
}
__device__ __forceinline__ float fast_tanh(float x) {
    const float e = __expf(-2.0f * x);
    return (1.0f - e) / (1.0f + e);
}

__global__ __launch_bounds__(128) void lstm_scan_kernel(
    const float* __restrict__ w_hh_f, const float* __restrict__ w_hh_b)
{
    const int dir  = blockIdx.x;         // 0 = forward, 1 = backward
    const int j    = threadIdx.x;        // gate index 0..127
    const int lane = j & 31;
    const int wid  = j >> 5;             // 0:i 1:f 2:g 3:o

    const float* __restrict__ w_hh = dir ? w_hh_b : w_hh_f;
    const float* __restrict__ pre  = g_pre[dir];
    float* __restrict__ hout       = g_h[dir];

    __shared__ float gs[2][G4];          // ping-pong gate buffer

    // w_hh row j -> registers
    float wr[H];
    #pragma unroll
    for (int k = 0; k < H; k++) wr[k] = w_hh[j * H + k];

    float h = 0.0f, c = 0.0f;

    // prefetch pre for step 0
    int idx = dir ? (S - 1) : 0;
    float pnext = pre[idx * G4 + j];

    for (int t = 0; t < S; t++) {
        const int cur = idx;
        const float p = pnext;
        // prefetch next step's pre (hide L2 latency under this step)
        idx = dir ? (S - 2 - t) : (t + 1);
        if (t + 1 < S) pnext = __ldg(&pre[idx * G4 + j]);

        // gate pre-activation: p + sum_k w[j][k] * h[k], h via warp shuffle
        float g = p;
        #pragma unroll
        for (int k = 0; k < H; k++)
            g = fmaf(wr[k], __shfl_sync(0xffffffffu, h, k), g);

        // activation (warp-uniform branch: warp 2 = tanh, others = sigmoid)
        const float a = (wid == 2) ? fast_tanh(g) : fast_sigmoid(g);

        const int b = t & 1;
        gs[b][j] = a;
        __syncthreads();

        // every warp redundantly updates (c, h) for its lane's unit
        const float gi = gs[b][lane];
        const float gf = gs[b][H + lane];
        const float gg = gs[b][2 * H + lane];
        const float go = gs[b][3 * H + lane];
        c = fmaf(gf, c, gi * gg);
        h = go * fast_tanh(c);

        if (j < H) hout[cur * H + lane] = h;
    }
}

// ---------------------------------------------------------------------------
// Kernel C: output projection  out[s,n] = [hf;hb] . out_w[n] + out_b[n]
// ---------------------------------------------------------------------------
__global__ __launch_bounds__(256) void out_kernel(
    const float* __restrict__ out_w, const float* __restrict__ out_b,
    float* __restrict__ out)
{
    const int i = blockIdx.x * blockDim.x + threadIdx.x;
    if (i >= S * NTAGS) return;
    const int s = i / NTAGS, n = i % NTAGS;
    const float* __restrict__ hf = &g_h[0][s * H];
    const float* __restrict__ hb = &g_h[1][s * H];
    const float* __restrict__ w  = out_w + n * 2 * H;
    float acc = out_b[n];
    #pragma unroll
    for (int k = 0; k < H; k++) acc = fmaf(hf[k], w[k], acc);
    #pragma unroll
    for (int k = 0; k < H; k++) acc = fmaf(hb[k], w[H + k], acc);
    out[i] = acc;
}

// ---------------------------------------------------------------------------
extern "C" void kernel_launch(void* const* d_in, const int* in_sizes, int n_in,
                              void* d_out, int out_size)
{
    const int*   word_ids = (const int*)  d_in[0];
    const int*   char_ids = (const int*)  d_in[1];
    const float* word_emb = (const float*)d_in[2];
    const float* char_emb = (const float*)d_in[3];
    const float* conv_w   = (const float*)d_in[4];
    const float* conv_b   = (const float*)d_in[5];
    const float* w_ih_f   = (const float*)d_in[6];
    const float* w_hh_f   = (const float*)d_in[7];
    const float* b_ih_f   = (const float*)d_in[8];
    const float* b_hh_f   = (const float*)d_in[9];
    const float* w_ih_b   = (const float*)d_in[10];
    const float* w_hh_b   = (const float*)d_in[11];
    const float* b_ih_b   = (const float*)d_in[12];
    const float* b_hh_b   = (const float*)d_in[13];
    const float* out_w    = (const float*)d_in[14];
    const float* out_b    = (const float*)d_in[15];
    float* out = (float*)d_out;

    prep_kernel<<<S, 128>>>(word_ids, char_ids, word_emb, char_emb,
                            conv_w, conv_b,
                            w_ih_f, b_ih_f, b_hh_f,
                            w_ih_b, b_ih_b, b_hh_b);
    lstm_scan_kernel<<<2, 128>>>(w_hh_f, w_hh_b);
    out_kernel<<<(S * NTAGS + 255) / 256, 256>>>(out_w, out_b, out);
}

// round 2
// speedup vs baseline: 1.3403x; 1.3403x over previous
#include <cuda_runtime.h>

#define S 4096
#define L 16
#define WD 128
#define CD 32
#define NF 5
#define KW 5
#define H 32
#define NTAGS 45
#define IN_DIM (WD + NF)   // 133
#define G4 (4 * H)         // 128
#define TS 32              // sentences per projection tile

// Scratch (device globals; no allocation allowed)
__device__ float g_rept[IN_DIM * S];   // rep transposed [k][s]  (2.2 MB)
__device__ float g_pre[2][S * G4];     // input projections, fwd/bwd (4 MB)
__device__ float g_h[2][S * H];        // hidden states, fwd/bwd (1 MB)

__device__ __forceinline__ float mufu_tanh(float x) {
    float y;
    asm("tanh.approx.f32 %0, %1;" : "=f"(y) : "f"(x));
    return y;
}
__device__ __forceinline__ float mufu_sigmoid(float x) {
    return fmaf(0.5f, mufu_tanh(0.5f * x), 0.5f);
}

// ---------------------------------------------------------------------------
// Kernel A: per-word embedding gather + char CNN -> rep, stored transposed
// grid = S blocks, 128 threads
// ---------------------------------------------------------------------------
__global__ __launch_bounds__(128) void rep_kernel(
    const int* __restrict__ word_ids, const int* __restrict__ char_ids,
    const float* __restrict__ word_emb, const float* __restrict__ char_emb,
    const float* __restrict__ conv_w, const float* __restrict__ conv_b)
{
    __shared__ float ce[L][CD];
    __shared__ float conv_sh[NF][L];

    const int s = blockIdx.x;
    const int j = threadIdx.x;   // 0..127

    // word embedding -> rep[0:128] (straight to transposed global)
    const int wid = word_ids[s];
    const float wv = word_emb[wid * WD + j];
    g_rept[j * S + s] = wv;

    // char embeddings: L*CD = 512 floats, 4 per thread
    #pragma unroll
    for (int i = j; i < L * CD; i += 128) {
        const int l = i / CD, c = i % CD;
        const int cid = char_ids[s * L + l];
        ce[l][c] = char_emb[cid * CD + c];
    }
    __syncthreads();

    // conv: NF*L = 80 outputs, one per thread
    if (j < NF * L) {
        const int f = j / L, l = j % L;
        float acc = conv_b[f];
        #pragma unroll
        for (int k = 0; k < KW; k++) {
            const int ll = l + k - 2;
            if (ll >= 0 && ll < L) {
                #pragma unroll
                for (int c = 0; c < CD; c++)
                    acc += ce[ll][c] * conv_w[(f * CD + c) * KW + k];
            }
        }
        conv_sh[f][l] = acc;
    }
    __syncthreads();

    // maxpool over L -> rep[128:133]
    if (j < NF) {
        float m = conv_sh[j][0];
        #pragma unroll
        for (int l = 1; l < L; l++) m = fmaxf(m, conv_sh[j][l]);
        g_rept[(WD + j) * S + s] = m;
    }
}

// ---------------------------------------------------------------------------
// Kernel A2: input projection GEMM. pre[d][s][j] = rep[s] . w_ih_d[j] + bias
// grid = S/TS blocks, 256 threads (thread o: dir = o>>7, gate j = o&127)
// Each thread computes TS=32 sentences for its gate. Weights stream through
// L1 (reused by all 128 blocks); rep tile staged in shared [k][s] for LDS.128.
// ---------------------------------------------------------------------------
__global__ __launch_bounds__(256) void proj_kernel(
    const float* __restrict__ w_ih_f, const float* __restrict__ b_ih_f,
    const float* __restrict__ b_hh_f,
    const float* __restrict__ w_ih_b, const float* __restrict__ b_ih_b,
    const float* __restrict__ b_hh_b)
{
    __shared__ float rt_sh[IN_DIM][TS];   // 133 x 32 floats (17 KB)

    const int s0  = blockIdx.x * TS;
    const int o   = threadIdx.x;
    const int dir = o >> 7;
    const int j   = o & 127;

    // stage rep tile (coalesced: 32 consecutive s per row)
    for (int i = o; i < IN_DIM * TS; i += 256) {
        const int k = i / TS, s = i % TS;
        rt_sh[k][s] = g_rept[k * S + s0 + s];
    }
    __syncthreads();

    const float bias = dir ? (b_ih_b[j] + b_hh_b[j]) : (b_ih_f[j] + b_hh_f[j]);
    const float* __restrict__ wrow = (dir ? w_ih_b : w_ih_f) + j * IN_DIM;

    float acc[TS];
    #pragma unroll
    for (int i = 0; i < TS; i++) acc[i] = bias;

    for (int k = 0; k < IN_DIM; k++) {
        const float w = __ldg(&wrow[k]);
        const float4* r4 = (const float4*)&rt_sh[k][0];
        #pragma unroll
        for (int q = 0; q < TS / 4; q++) {
            const float4 r = r4[q];
            acc[4 * q + 0] = fmaf(w, r.x, acc[4 * q + 0]);
            acc[4 * q + 1] = fmaf(w, r.y, acc[4 * q + 1]);
            acc[4 * q + 2] = fmaf(w, r.z, acc[4 * q + 2]);
            acc[4 * q + 3] = fmaf(w, r.w, acc[4 * q + 3]);
        }
    }

    float* __restrict__ pre = g_pre[dir];
    #pragma unroll
    for (int i = 0; i < TS; i++)
        pre[(s0 + i) * G4 + j] = acc[i];
}

// ---------------------------------------------------------------------------
// Kernel B: sequential LSTM scan. grid = 2 blocks (dir), 128 threads.
// Thread j owns gate j (w_hh row in registers). All 4 warps redundantly
// carry (h, c) for unit `lane`; matvec via intra-warp shuffles, 4 accumulators
// to break the FMA dependency chain. One __syncthreads per step (ping-pong
// gate buffer). All activations via MUFU tanh.approx.
// ---------------------------------------------------------------------------
__global__ __launch_bounds__(128) void lstm_scan_kernel(
    const float* __restrict__ w_hh_f, const float* __restrict__ w_hh_b)
{
    const int dir  = blockIdx.x;
    const int j    = threadIdx.x;
    const int lane = j & 31;
    const int wid  = j >> 5;             // 0:i 1:f 2:g 3:o

    const float* __restrict__ w_hh = dir ? w_hh_b : w_hh_f;
    const float* __restrict__ pre  = g_pre[dir];
    float* __restrict__ hout       = g_h[dir];

    __shared__ float gs[2][G4];          // ping-pong gate buffer

    float wr[H];
    #pragma unroll
    for (int k = 0; k < H; k++) wr[k] = w_hh[j * H + k];

    float h = 0.0f, c = 0.0f;

    int idx = dir ? (S - 1) : 0;
    float pnext = pre[idx * G4 + j];

    for (int t = 0; t < S; t++) {
        const int cur = idx;
        const float p = pnext;
        idx = dir ? (S - 2 - t) : (t + 1);
        if (t + 1 < S) pnext = __ldg(&pre[idx * G4 + j]);

        // gate pre-activation: 4 independent accumulator chains
        float a0 = p, a1 = 0.0f, a2 = 0.0f, a3 = 0.0f;
        #pragma unroll
        for (int k = 0; k < H; k += 4) {
            a0 = fmaf(wr[k + 0], __shfl_sync(0xffffffffu, h, k + 0), a0);
            a1 = fmaf(wr[k + 1], __shfl_sync(0xffffffffu, h, k + 1), a1);
            a2 = fmaf(wr[k + 2], __shfl_sync(0xffffffffu, h, k + 2), a2);
            a3 = fmaf(wr[k + 3], __shfl_sync(0xffffffffu, h, k + 3), a3);
        }
        const float g = (a0 + a1) + (a2 + a3);

        // warp-uniform: warp 2 = tanh gate, others = sigmoid
        const float a = (wid == 2) ? mufu_tanh(g) : mufu_sigmoid(g);

        const int b = t & 1;
        gs[b][j] = a;
        __syncthreads();

        const float gi = gs[b][lane];
        const float gf = gs[b][H + lane];
        const float gg = gs[b][2 * H + lane];
        const float go = gs[b][3 * H + lane];
        c = fmaf(gf, c, gi * gg);
        h = go * mufu_tanh(c);

        if (j < H) hout[cur * H + lane] = h;
    }
}

// ---------------------------------------------------------------------------
// Kernel C: output projection  out[s,n] = [hf;hb] . out_w[n] + out_b[n]
// ---------------------------------------------------------------------------
__global__ __launch_bounds__(256) void out_kernel(
    const float* __restrict__ out_w, const float* __restrict__ out_b,
    float* __restrict__ out)
{
    const int i = blockIdx.x * blockDim.x + threadIdx.x;
    if (i >= S * NTAGS) return;
    const int s = i / NTAGS, n = i % NTAGS;
    const float* __restrict__ hf = &g_h[0][s * H];
    const float* __restrict__ hb = &g_h[1][s * H];
    const float* __restrict__ w  = out_w + n * 2 * H;
    float acc = out_b[n];
    #pragma unroll
    for (int k = 0; k < H; k++) acc = fmaf(hf[k], w[k], acc);
    #pragma unroll
    for (int k = 0; k < H; k++) acc = fmaf(hb[k], w[H + k], acc);
    out[i] = acc;
}

// ---------------------------------------------------------------------------
extern "C" void kernel_launch(void* const* d_in, const int* in_sizes, int n_in,
                              void* d_out, int out_size)
{
    const int*   word_ids = (const int*)  d_in[0];
    const int*   char_ids = (const int*)  d_in[1];
    const float* word_emb = (const float*)d_in[2];
    const float* char_emb = (const float*)d_in[3];
    const float* conv_w   = (const float*)d_in[4];
    const float* conv_b   = (const float*)d_in[5];
    const float* w_ih_f   = (const float*)d_in[6];
    const float* w_hh_f   = (const float*)d_in[7];
    const float* b_ih_f   = (const float*)d_in[8];
    const float* b_hh_f   = (const float*)d_in[9];
    const float* w_ih_b   = (const float*)d_in[10];
    const float* w_hh_b   = (const float*)d_in[11];
    const float* b_ih_b   = (const float*)d_in[12];
    const float* b_hh_b   = (const float*)d_in[13];
    const float* out_w    = (const float*)d_in[14];
    const float* out_b    = (const float*)d_in[15];
    float* out = (float*)d_out;

    rep_kernel<<<S, 128>>>(word_ids, char_ids, word_emb, char_emb,
                           conv_w, conv_b);
    proj_kernel<<<S / TS, 256>>>(w_ih_f, b_ih_f, b_hh_f,
                                 w_ih_b, b_ih_b, b_hh_b);
    lstm_scan_kernel<<<2, 128>>>(w_hh_f, w_hh_b);
    out_kernel<<<(S * NTAGS + 255) / 256, 256>>>(out_w, out_b, out);
}

// round 3
// speedup vs baseline: 1.9492x; 1.4543x over previous
#include <cuda_runtime.h>

#define S 4096
#define L 16
#define WD 128
#define CD 32
#define NF 5
#define KW 5
#define H 32
#define NTAGS 45
#define IN_DIM (WD + NF)   // 133
#define G4 (4 * H)         // 128
#define TS 32              // sentences per projection tile

// Scratch (device globals; no allocation allowed)
__device__ float g_rept[IN_DIM * S];       // rep transposed [k][s]
__device__ float g_pre[2][S * G4];         // input projections, layout [s][unit][gate]
__device__ float g_h[2][S * H];            // hidden states

typedef unsigned long long u64;

__device__ __forceinline__ float mufu_tanh(float x) {
    float y;
    asm("tanh.approx.f32 %0, %1;" : "=f"(y) : "f"(x));
    return y;
}
__device__ __forceinline__ float mufu_sigmoid(float x) {
    return fmaf(0.5f, mufu_tanh(0.5f * x), 0.5f);
}
__device__ __forceinline__ u64 pack2(float lo, float hi) {
    u64 r;
    asm("mov.b64 %0, {%1, %2};" : "=l"(r) : "f"(lo), "f"(hi));
    return r;
}
__device__ __forceinline__ void unpack2(float& lo, float& hi, u64 v) {
    asm("mov.b64 {%0, %1}, %2;" : "=f"(lo), "=f"(hi) : "l"(v));
}
__device__ __forceinline__ void fma2(u64& acc, u64 a, u64 b) {
    asm("fma.rn.f32x2 %0, %1, %2, %0;" : "+l"(acc) : "l"(a), "l"(b));
}

// ---------------------------------------------------------------------------
// Kernel A: per-word embedding gather + char CNN -> rep (transposed [k][s])
// ---------------------------------------------------------------------------
__global__ __launch_bounds__(128) void rep_kernel(
    const int* __restrict__ word_ids, const int* __restrict__ char_ids,
    const float* __restrict__ word_emb, const float* __restrict__ char_emb,
    const float* __restrict__ conv_w, const float* __restrict__ conv_b)
{
    __shared__ float ce[L][CD];
    __shared__ float conv_sh[NF][L];

    const int s = blockIdx.x;
    const int j = threadIdx.x;

    const int wid = word_ids[s];
    g_rept[j * S + s] = word_emb[wid * WD + j];

    #pragma unroll
    for (int i = j; i < L * CD; i += 128) {
        const int l = i / CD, c = i % CD;
        const int cid = char_ids[s * L + l];
        ce[l][c] = char_emb[cid * CD + c];
    }
    __syncthreads();

    if (j < NF * L) {
        const int f = j / L, l = j % L;
        float acc = conv_b[f];
        #pragma unroll
        for (int k = 0; k < KW; k++) {
            const int ll = l + k - 2;
            if (ll >= 0 && ll < L) {
                #pragma unroll
                for (int c = 0; c < CD; c++)
                    acc += ce[ll][c] * conv_w[(f * CD + c) * KW + k];
            }
        }
        conv_sh[f][l] = acc;
    }
    __syncthreads();

    if (j < NF) {
        float m = conv_sh[j][0];
        #pragma unroll
        for (int l = 1; l < L; l++) m = fmaxf(m, conv_sh[j][l]);
        g_rept[(WD + j) * S + s] = m;
    }
}

// ---------------------------------------------------------------------------
// Kernel A2: input projection GEMM. Writes pre in [s][unit][gate] layout.
// ---------------------------------------------------------------------------
__global__ __launch_bounds__(256) void proj_kernel(
    const float* __restrict__ w_ih_f, const float* __restrict__ b_ih_f,
    const float* __restrict__ b_hh_f,
    const float* __restrict__ w_ih_b, const float* __restrict__ b_ih_b,
    const float* __restrict__ b_hh_b)
{
    __shared__ float rt_sh[IN_DIM][TS];

    const int s0  = blockIdx.x * TS;
    const int o   = threadIdx.x;
    const int dir = o >> 7;
    const int j   = o & 127;          // original gate row: 0..31 i, 32..63 f, ...

    for (int i = o; i < IN_DIM * TS; i += 256) {
        const int k = i / TS, s = i % TS;
        rt_sh[k][s] = g_rept[k * S + s0 + s];
    }
    __syncthreads();

    const float bias = dir ? (b_ih_b[j] + b_hh_b[j]) : (b_ih_f[j] + b_hh_f[j]);
    const float* __restrict__ wrow = (dir ? w_ih_b : w_ih_f) + j * IN_DIM;

    float acc[TS];
    #pragma unroll
    for (int i = 0; i < TS; i++) acc[i] = bias;

    for (int k = 0; k < IN_DIM; k++) {
        const float w = __ldg(&wrow[k]);
        const float4* r4 = (const float4*)&rt_sh[k][0];
        #pragma unroll
        for (int q = 0; q < TS / 4; q++) {
            const float4 r = r4[q];
            acc[4 * q + 0] = fmaf(w, r.x, acc[4 * q + 0]);
            acc[4 * q + 1] = fmaf(w, r.y, acc[4 * q + 1]);
            acc[4 * q + 2] = fmaf(w, r.z, acc[4 * q + 2]);
            acc[4 * q + 3] = fmaf(w, r.w, acc[4 * q + 3]);
        }
    }

    // interleaved write: pre[s*128 + unit*4 + gate]
    const int unit = j & 31, gate = j >> 5;
    float* __restrict__ pre = g_pre[dir];
    #pragma unroll
    for (int i = 0; i < TS; i++)
        pre[(s0 + i) * G4 + unit * 4 + gate] = acc[i];
}

// ---------------------------------------------------------------------------
// Kernel B: LSTM scan, ONE WARP per direction, zero barriers.
// Lane l owns unit l: all 4 gate rows of w_hh in registers as f32x2 pairs.
// h broadcast via warp shuffles; gates via fma.rn.f32x2 (2 MACs/instr).
// ---------------------------------------------------------------------------
__global__ __launch_bounds__(32, 1) void lstm_scan_kernel(
    const float* __restrict__ w_hh_f, const float* __restrict__ w_hh_b)
{
    const int dir  = blockIdx.x;
    const int lane = threadIdx.x;    // unit index 0..31

    const float* __restrict__ w_hh = dir ? w_hh_b : w_hh_f;
    const float* __restrict__ pre  = g_pre[dir];
    float* __restrict__ hout       = g_h[dir];

    // Load gate rows for this unit, packed as f32x2 pairs
    u64 wi[H / 2], wf[H / 2], wg[H / 2], wo[H / 2];
    #pragma unroll
    for (int m = 0; m < H / 2; m++) {
        wi[m] = pack2(w_hh[(0 * H + lane) * H + 2 * m], w_hh[(0 * H + lane) * H + 2 * m + 1]);
        wf[m] = pack2(w_hh[(1 * H + lane) * H + 2 * m], w_hh[(1 * H + lane) * H + 2 * m + 1]);
        wg[m] = pack2(w_hh[(2 * H + lane) * H + 2 * m], w_hh[(2 * H + lane) * H + 2 * m + 1]);
        wo[m] = pack2(w_hh[(3 * H + lane) * H + 2 * m], w_hh[(3 * H + lane) * H + 2 * m + 1]);
    }

    float h = 0.0f, c = 0.0f;

    int idx = dir ? (S - 1) : 0;
    float4 pv = *(const float4*)&pre[idx * G4 + lane * 4];   // (i,f,g,o) for this unit

    for (int t = 0; t < S; t++) {
        const int cur = idx;
        const float4 p = pv;
        idx = dir ? (S - 2 - t) : (t + 1);
        if (t + 1 < S) pv = *(const float4*)&pre[idx * G4 + lane * 4];

        // gate pre-activations: acc2 packed pairs, init (pre, 0)
        u64 ai = pack2(p.x, 0.0f);
        u64 af = pack2(p.y, 0.0f);
        u64 ag = pack2(p.z, 0.0f);
        u64 ao = pack2(p.w, 0.0f);

        #pragma unroll
        for (int m = 0; m < H / 2; m++) {
            const float ha = __shfl_sync(0xffffffffu, h, 2 * m);
            const float hb = __shfl_sync(0xffffffffu, h, 2 * m + 1);
            const u64 h2 = pack2(ha, hb);
            fma2(ai, wi[m], h2);
            fma2(af, wf[m], h2);
            fma2(ag, wg[m], h2);
            fma2(ao, wo[m], h2);
        }

        float lo, hi;
        unpack2(lo, hi, ai); const float gi = mufu_sigmoid(lo + hi);
        unpack2(lo, hi, af); const float gf = mufu_sigmoid(lo + hi);
        unpack2(lo, hi, ag); const float gg = mufu_tanh(lo + hi);
        unpack2(lo, hi, ao); const float go = mufu_sigmoid(lo + hi);

        c = fmaf(gf, c, gi * gg);
        h = go * mufu_tanh(c);

        hout[cur * H + lane] = h;
    }
}

// ---------------------------------------------------------------------------
// Kernel C: output projection, shared-staged. Block = 32 sentences.
// ---------------------------------------------------------------------------
__global__ __launch_bounds__(256) void out_kernel(
    const float* __restrict__ out_w, const float* __restrict__ out_b,
    float* __restrict__ out)
{
    __shared__ float hsh[32][66];          // [s][hf(0:32)|hb(32:64)], padded
    __shared__ float wsh[NTAGS * 65];      // [n][k], padded rows
    __shared__ float bsh[NTAGS];

    const int s0  = blockIdx.x * 32;
    const int tid = threadIdx.x;

    for (int i = tid; i < 32 * H; i += 256) {
        const int s = i >> 5, k = i & 31;
        hsh[s][k]     = g_h[0][(s0 + s) * H + k];
        hsh[s][32 + k] = g_h[1][(s0 + s) * H + k];
    }
    for (int i = tid; i < NTAGS * 2 * H; i += 256)
        wsh[(i >> 6) * 65 + (i & 63)] = out_w[i];
    if (tid < NTAGS) bsh[tid] = out_b[tid];
    __syncthreads();

    for (int o = tid; o < 32 * NTAGS; o += 256) {
        const int s = o / NTAGS, n = o % NTAGS;
        float acc = bsh[n];
        const float* __restrict__ hv = hsh[s];
        const float* __restrict__ wv = &wsh[n * 65];
        #pragma unroll
        for (int k = 0; k < 2 * H; k++) acc = fmaf(hv[k], wv[k], acc);
        out[(s0 + s) * NTAGS + n] = acc;
    }
}

// ---------------------------------------------------------------------------
extern "C" void kernel_launch(void* const* d_in, const int* in_sizes, int n_in,
                              void* d_out, int out_size)
{
    const int*   word_ids = (const int*)  d_in[0];
    const int*   char_ids = (const int*)  d_in[1];
    const float* word_emb = (const float*)d_in[2];
    const float* char_emb = (const float*)d_in[3];
    const float* conv_w   = (const float*)d_in[4];
    const float* conv_b   = (const float*)d_in[5];
    const float* w_ih_f   = (const float*)d_in[6];
    const float* w_hh_f   = (const float*)d_in[7];
    const float* b_ih_f   = (const float*)d_in[8];
    const float* b_hh_f   = (const float*)d_in[9];
    const float* w_ih_b   = (const float*)d_in[10];
    const float* w_hh_b   = (const float*)d_in[11];
    const float* b_ih_b   = (const float*)d_in[12];
    const float* b_hh_b   = (const float*)d_in[13];
    const float* out_w    = (const float*)d_in[14];
    const float* out_b    = (const float*)d_in[15];
    float* out = (float*)d_out;

    rep_kernel<<<S, 128>>>(word_ids, char_ids, word_emb, char_emb,
                           conv_w, conv_b);
    proj_kernel<<<S / TS, 256>>>(w_ih_f, b_ih_f, b_hh_f,
                                 w_ih_b, b_ih_b, b_hh_b);
    lstm_scan_kernel<<<2, 32>>>(w_hh_f, w_hh_b);
    out_kernel<<<S / 32, 256>>>(out_w, out_b, out);
}